// round 7
// baseline (speedup 1.0000x reference)
#include <cuda_runtime.h>
#include <math.h>

#define TF   481
#define NK   48
#define NT   192
#define ADJS 482            // adjT row stride (f-major), col 481 zero-padded
#define BROW 100
#define NP   241            // total f-pairs (482/2)
#define TILEP 32            // f-pairs per tile
#define NTILE 8             // 7*32 + 17
#define QROW 132            // bsm row stride per q (32 P * 4 floats + 4 pad)
#define BTILE (48*QROW)     // 6336 floats per band tile

// smem map (floats)
#define OFF_ADJT 0                         // 2*16*482 = 15424
#define OFF_BSM  15424                     // 6336
#define OFF_C2   21760                     // 512
#define SMEMF    22272                     // 89.1 KB
// overlays (dead after GEMM)
#define OFF_CPART OFF_ADJT                 // 4*16*100 = 6400 (over adjT)
#define OFF_CF    OFF_BSM                  // 2*1600 = 3200 (over bsm)
#define OFF_QSM   (OFF_BSM + 3200)         // 2*1536 = 3072 (fits 6336-3200)

__device__ float g_bprep[NTILE * BTILE];   // pre-tiled packed band

// f32x2 packed FMA: acc += a * b (2 independent fp32 lanes, IEEE rn)
#define FMA2(acc, a, b) \
    asm("fma.rn.f32x2 %0, %1, %2, %0;" : "+l"(acc) : "l"(a), "l"(b))

__device__ __forceinline__ float2 u2f(unsigned long long v) {
    float2 r;
    asm("mov.b64 {%0, %1}, %2;" : "=f"(r.x), "=f"(r.y) : "l"(v));
    return r;
}

// ---------------- prep: band -> tiled packed layout ----------------
// g_bprep[t][q*QROW + P*4 + j]:
//   j=0: b[f][2q]  j=1: b[f+1][2q]  j=2: b[f][2q+1]  j=3: b[f+1][2q+1]
//   where f = 2*(t*TILEP + P); interleaved n: even=bandR[k], odd=bandI[k], k=n>>1.
__global__ void pv_prep(const float* __restrict__ bandR, const float* __restrict__ bandI)
{
    int i = blockIdx.x * 256 + threadIdx.x;
    if (i >= NTILE * BTILE) return;
    int t = i / BTILE, r = i % BTILE;
    int q = r / QROW, w = r % QROW;
    float val = 0.0f;
    if (w < TILEP * 4) {
        int P = w >> 2, j = w & 3;
        int f = 2 * (t * TILEP + P) + (j & 1);
        int n = 2 * q + (j >> 1);
        if (f < TF)
            val = (n & 1) ? bandI[f * NK + (n >> 1)] : bandR[f * NK + (n >> 1)];
    }
    g_bprep[i] = val;
}

// ---------------- stage 1: two frames per block, f32x2 GEMM ----------------
__global__ __launch_bounds__(NT) void pv_stage1(
    const float* __restrict__ binsR, const float* __restrict__ binsI,
    const float* __restrict__ c2r,  const float* __restrict__ c2i,
    float* __restrict__ out)
{
    extern __shared__ float sm[];
    float* adjT = sm + OFF_ADJT;   // [tl][c][f]
    float* bsm  = sm + OFF_BSM;
    float* c2sm = sm + OFF_C2;

    const int tid = threadIdx.x;
    const int bt0 = blockIdx.x * 2;
    const int b   = bt0 >> 10;
    const int t0  = bt0 & 1023;

    // c2pv transposed: c2sm[c*16+p] = c2r[p*16+c]; imag at +256
    for (int i = tid; i < 512; i += NT) {
        int v = i & 255;
        int p = v >> 4, c = v & 15;
        float val = (i < 256) ? c2r[i] : c2i[v];
        c2sm[(i < 256 ? 0 : 256) + c * 16 + p] = val;
    }

    // ---- fused phase 1+2: adjT from x (recompute neighbors, unnormalized angle) ----
    for (int u = tid; u < 2 * TF; u += NT) {
        int tl = 0, f = u;
        if (f >= TF) { f -= TF; tl = 1; }
        const float* xr = binsR + (size_t)(bt0 + tl) * 4 * TF;
        const float* xi = binsI + (size_t)(bt0 + tl) * 4 * TF;
        int lo = (f == 0) ? 0 : ((f == TF-1) ? TF-3 : f-1);
        int hi = lo + 2;

        float r0 = xr[f],      i0 = xi[f];
        float r1 = xr[TF+f],   i1 = xi[TF+f];
        float r2 = xr[2*TF+f], i2 = xi[2*TF+f];
        float r3 = xr[3*TF+f], i3 = xi[3*TF+f];
        float d0 = r0*r0 + i0*i0;
        float d1 = r1*r1 + i1*i1;
        float d2 = r2*r2 + i2*i2;
        float d3 = r3*r3 + i3*i3;
        float inv = 1.0f / fmaxf(d0+d1+d2+d3, 1e-20f);

        float pr[6], pi[6];
#define PR(s,Ri,Ii,Rj,Ij) pr[s] = Ri*Rj + Ii*Ij; pi[s] = Ii*Rj - Ri*Ij;
        PR(0,r0,i0,r1,i1) PR(1,r0,i0,r2,i2) PR(2,r0,i0,r3,i3)
        PR(3,r1,i1,r2,i2) PR(4,r1,i1,r3,i3) PR(5,r2,i2,r3,i3)
#undef PR
        float lr[6], li[6], hr[6], hix[6];
        {
            float a0 = xr[lo],      b0 = xi[lo];
            float a1 = xr[TF+lo],   b1 = xi[TF+lo];
            float a2 = xr[2*TF+lo], b2 = xi[2*TF+lo];
            float a3 = xr[3*TF+lo], b3 = xi[3*TF+lo];
#define PL(s,Ri,Ii,Rj,Ij) lr[s] = Ri*Rj + Ii*Ij; li[s] = Ii*Rj - Ri*Ij;
            PL(0,a0,b0,a1,b1) PL(1,a0,b0,a2,b2) PL(2,a0,b0,a3,b3)
            PL(3,a1,b1,a2,b2) PL(4,a1,b1,a3,b3) PL(5,a2,b2,a3,b3)
#undef PL
            a0 = xr[hi];      b0 = xi[hi];
            a1 = xr[TF+hi];   b1 = xi[TF+hi];
            a2 = xr[2*TF+hi]; b2 = xi[2*TF+hi];
            a3 = xr[3*TF+hi]; b3 = xi[3*TF+hi];
#define PH(s,Ri,Ii,Rj,Ij) hr[s] = Ri*Rj + Ii*Ij; hix[s] = Ii*Rj - Ri*Ij;
            PH(0,a0,b0,a1,b1) PH(1,a0,b0,a2,b2) PH(2,a0,b0,a3,b3)
            PH(3,a1,b1,a2,b2) PH(4,a1,b1,a3,b3) PH(5,a2,b2,a3,b3)
#undef PH
        }

        float* base = adjT + tl * 16 * ADJS;
        #pragma unroll
        for (int s = 0; s < 6; s++) {
            float zr = lr[s]*hr[s] + li[s]*hix[s];
            float zi = lr[s]*hix[s] - li[s]*hr[s];
            float m  = sqrtf(pr[s]*pr[s] + pi[s]*pi[s]) * inv;
            float z2 = zr*zr + zi*zi;
            float aR, aI;
            if (z2 > 0.0f) {
                float sc = m * rsqrtf(z2);
                aR = sc*zr; aI = sc*zi;
            } else {
                aR = m; aI = 0.0f;
            }
            base[(2*s)*ADJS + f]   = aR;
            base[(2*s+1)*ADJS + f] = aI;
        }
        base[12*ADJS + f] = d0*inv;
        base[13*ADJS + f] = d1*inv;
        base[14*ADJS + f] = d2*inv;
        base[15*ADJS + f] = d3*inv;
    }
    // zero pad column f=481
    if (tid < 32) {
        int tl = tid >> 4, c = tid & 15;
        adjT[(tl*16 + c)*ADJS + (TF)] = 0.0f;   // f = 481
    }
    __syncthreads();

    // ---- GEMM: C[tl][16][96] = sum_f adjT[tl][c][f] * band[f][n], f32x2 over f-pairs ----
    // thread: q = tid%48 (n-pair 2q,2q+1); gm = tid/48: g = gm&1 (f-pair split), m2 = gm>>1
    const int q  = tid % 48;
    const int gm = tid / 48;
    const int g  = gm & 1;
    const int m2 = gm >> 1;

    unsigned long long acc[2][8][2];
    #pragma unroll
    for (int tl = 0; tl < 2; tl++)
        #pragma unroll
        for (int u = 0; u < 8; u++) { acc[tl][u][0] = 0ULL; acc[tl][u][1] = 0ULL; }

    const float* a0base = adjT + (m2*8)*ADJS;          // tl=0 rows
    const float* a1base = a0base + 16*ADJS;            // tl=1 rows

    for (int tile = 0; tile < NTILE; ++tile) {
        const int lenP = (tile < 7) ? TILEP : (NP - 7*TILEP);
        __syncthreads();
        {
            const float4* src = (const float4*)(g_bprep + tile*BTILE);
            float4* dst = (float4*)bsm;
            for (int i = tid; i < BTILE/4; i += NT) dst[i] = src[i];
        }
        __syncthreads();
        const int f_base = tile * (2*TILEP);
        const float* bq = bsm + q*QROW;
        #pragma unroll 2
        for (int P = g; P < lenP; P += 2) {
            ulonglong2 bb = *(const ulonglong2*)(bq + P*4);
            const int f0 = f_base + 2*P;
            #pragma unroll
            for (int u = 0; u < 8; u++) {
                unsigned long long av0 =
                    *(const unsigned long long*)(a0base + u*ADJS + f0);
                FMA2(acc[0][u][0], av0, bb.x);
                FMA2(acc[0][u][1], av0, bb.y);
                unsigned long long av1 =
                    *(const unsigned long long*)(a1base + u*ADJS + f0);
                FMA2(acc[1][u][0], av1, bb.x);
                FMA2(acc[1][u][1], av1, bb.y);
            }
        }
    }
    __syncthreads();

    // ---- reduce: unpack f32x2 halves, write partials, sum over g ----
    float* Cpart = sm + OFF_CPART;     // [(g*2+tl)][m][BROW]
    #pragma unroll
    for (int tl = 0; tl < 2; tl++)
        #pragma unroll
        for (int u = 0; u < 8; u++) {
            float2 v0 = u2f(acc[tl][u][0]);
            float2 v1 = u2f(acc[tl][u][1]);
            int m = m2*8 + u;
            *(float2*)&Cpart[((g*2 + tl)*16 + m)*BROW + 2*q] =
                make_float2(v0.x + v0.y, v1.x + v1.y);
        }
    __syncthreads();
    for (int idx = tid; idx < 2*16*96; idx += NT) {
        int tl = idx / 1536, r = idx % 1536;
        int m = r / 96, n = r % 96;
        sm[OFF_CF + tl*1600 + m*BROW + n] =
            Cpart[((0*2+tl)*16 + m)*BROW + n] + Cpart[((1*2+tl)*16 + m)*BROW + n];
    }
    __syncthreads();

    // ---- phase 4: reconstruct bc(complex 16) per k ----
    for (int w = tid; w < 2*192; w += NT) {
        int tl = w / 192, rr = w % 192;
        int kp = rr >> 3, slot = rr & 7;
        const float* Cfin = sm + OFF_CF + tl*1600;
        float* qsm = sm + OFF_QSM + tl*1536;
        int m0 = (slot < 6) ? 2*slot : 12 + 2*(slot-6);
        float4 rA = *(const float4*)&Cfin[m0*BROW + 4*kp];
        float4 rB = *(const float4*)&Cfin[(m0+1)*BROW + 4*kp];
        float A0=rA.x, A1=rA.y, A4=rA.z, A5=rA.w;
        float A2=rB.x, A3=rB.y, A6=rB.z, A7=rB.w;
        float* q0 = qsm + (2*kp)*32;
        float* q1 = q0 + 32;
        if (slot < 6) {
            int i = (slot < 3) ? 0 : ((slot < 5) ? 1 : 2);
            int j = (slot < 3) ? slot+1 : ((slot < 5) ? slot-1 : 3);
            int c1 = i*4 + j, c2 = j*4 + i;
            q0[c1] = A0 - A3; q0[16+c1] = A1 + A2;
            q0[c2] = A0 + A3; q0[16+c2] = A1 - A2;
            q1[c1] = A4 - A7; q1[16+c1] = A5 + A6;
            q1[c2] = A4 + A7; q1[16+c2] = A5 - A6;
        } else {
            int d  = (slot == 6) ? 0 : 2;
            int cA = d*5, cB = (d+1)*5;
            q0[cA] = A0; q0[16+cA] = A1; q0[cB] = A2; q0[16+cB] = A3;
            q1[cA] = A4; q1[16+cA] = A5; q1[cB] = A6; q1[16+cB] = A7;
        }
    }
    __syncthreads();

    // ---- phase 5: normalize + c2pv projection (real part) ----
    for (int o = tid; o < 2*NK*16; o += NT) {
        int tl = o / 768, r = o % 768;
        int k = r >> 4, p = r & 15;
        const float* qk = sm + OFF_QSM + tl*1536 + k*32;
        float ds = fmaxf(qk[0] + qk[5] + qk[10] + qk[15], 1e-20f);
        float acc2 = 0.0f;
        #pragma unroll
        for (int c = 0; c < 16; c++) {
            acc2 += c2sm[c*16 + p] * qk[c];
            acc2 -= c2sm[256 + c*16 + p] * qk[16 + c];
        }
        out[(((size_t)b*NK + k)*1024 + (t0 + tl))*16 + p] = acc2 / ds;
    }
}

// ---------------- stage 2: chunked parallel-scan IIR ----------------
__global__ __launch_bounds__(512) void pv_iir(float* __restrict__ out,
                                              const float* __restrict__ tau)
{
    __shared__ float tails[32*16];
    __shared__ float carry[32*16];
    const int bk  = blockIdx.x;          // b*NK + k
    const int k   = bk % NK;
    const int tid = threadIdx.x;
    const int chunk = tid >> 4, p = tid & 15;

    const float a  = expf(-10.0f / tau[k]);
    const float om = 1.0f - a;
    float* base = out + ((size_t)bk * 1024 + chunk * 32) * 16 + p;

    float x[32];
    #pragma unroll
    for (int j = 0; j < 32; j++) x[j] = base[j*16];

    float l[32];
    l[0] = (chunk == 0) ? x[0] : om * x[0];
    #pragma unroll
    for (int j = 1; j < 32; j++) l[j] = a*l[j-1] + om*x[j];

    tails[chunk*16 + p] = l[31];
    __syncthreads();

    if (tid < 16) {
        float A = expf(-320.0f / tau[k]);   // a^32
        float s = 0.0f;
        #pragma unroll
        for (int c = 0; c < 32; c++) {
            carry[c*16 + tid] = s;
            s = tails[c*16 + tid] + A * s;
        }
    }
    __syncthreads();

    float cin = carry[chunk*16 + p];
    float pw = a;
    #pragma unroll
    for (int j = 0; j < 32; j++) {
        base[j*16] = l[j] + pw * cin;
        pw *= a;
    }
}

extern "C" void kernel_launch(void* const* d_in, const int* in_sizes, int n_in,
                              void* d_out, int out_size)
{
    const float* binsR = (const float*)d_in[0];
    const float* binsI = (const float*)d_in[1];
    const float* bandR = (const float*)d_in[2];
    const float* bandI = (const float*)d_in[3];
    const float* c2r   = (const float*)d_in[4];
    const float* c2i   = (const float*)d_in[5];
    const float* tau   = (const float*)d_in[6];
    float* out = (float*)d_out;

    size_t smem = SMEMF * sizeof(float);   // ~89.1 KB
    cudaFuncSetAttribute(pv_stage1, cudaFuncAttributeMaxDynamicSharedMemorySize, (int)smem);

    pv_prep<<<(NTILE*BTILE + 255)/256, 256>>>(bandR, bandI);
    pv_stage1<<<2048, NT, smem>>>(binsR, binsI, c2r, c2i, out);
    pv_iir<<<4*NK, 512>>>(out, tau);
}

// round 9
// speedup vs baseline: 2.1631x; 2.1631x over previous
#include <cuda_runtime.h>
#include <cuda_bf16.h>
#include <math.h>
#include <cstdint>

#define TF 481
#define NK 48
#define NFR 4             // frames per block
#define NT 256
#define KT 64             // K cols per tile
#define NTILE 8           // 512 padded K
#define BROW 100

#define ARS 144           // A/B smem row stride bytes (72 bf16: 64 data + 8 pad)
// smem map (bytes)
#define SM_A_HI 0         // 64*144 = 9216
#define SM_A_LO 9216
#define SM_B_HI 18432     // 96*144 = 13824
#define SM_B_LO 32256
#define SM_C2B  50176     // 512 floats
#define SMEM_BYTES 52224
// overlays (A/B dead after last MMA)
#define SM_CF  0          // 4*16*100 floats = 25600 B
#define SM_QSM 25600      // 4*48*32 floats = 24576 B -> 50176

__device__ __align__(16) __nv_bfloat16 g_bt[2 * 96 * 512];   // [split][n][k]

// ---------------- prep: band -> bf16 hi/lo, interleaved n, padded K ----------------
__global__ void pv_prep(const float* __restrict__ bandR, const float* __restrict__ bandI)
{
    int i = blockIdx.x * 256 + threadIdx.x;
    if (i >= 96 * 512) return;
    int n = i >> 9, k = i & 511;
    float val = 0.0f;
    if (k < TF) val = (n & 1) ? bandI[k*NK + (n>>1)] : bandR[k*NK + (n>>1)];
    __nv_bfloat16 h = __float2bfloat16(val);
    __nv_bfloat16 l = __float2bfloat16(val - __bfloat162float(h));
    g_bt[i] = h;
    g_bt[96*512 + i] = l;
}

__device__ __forceinline__ void mma16816(float* c, const uint32_t* a, const uint32_t* b)
{
    asm volatile(
        "mma.sync.aligned.m16n8k16.row.col.f32.bf16.bf16.f32 "
        "{%0,%1,%2,%3}, {%4,%5,%6,%7}, {%8,%9}, {%0,%1,%2,%3};"
        : "+f"(c[0]), "+f"(c[1]), "+f"(c[2]), "+f"(c[3])
        : "r"(a[0]), "r"(a[1]), "r"(a[2]), "r"(a[3]), "r"(b[0]), "r"(b[1]));
}

// ---------------- stage 1: 4 frames per block, HMMA bf16-split GEMM ----------------
__global__ __launch_bounds__(NT) void pv_stage1(
    const float* __restrict__ binsR, const float* __restrict__ binsI,
    const float* __restrict__ c2r,  const float* __restrict__ c2i,
    float* __restrict__ out)
{
    extern __shared__ char smraw[];
    float* c2sm = (float*)(smraw + SM_C2B);

    const int tid = threadIdx.x;
    const int bt0 = blockIdx.x * NFR;
    const int b   = bt0 >> 10;
    const int t0  = bt0 & 1023;

    for (int i = tid; i < 512; i += NT) {
        int v = i & 255;
        int p = v >> 4, c = v & 15;
        float val = (i < 256) ? c2r[i] : c2i[v];
        c2sm[(i < 256 ? 0 : 256) + c*16 + p] = val;
    }

    const int fr = tid >> 6;       // frame 0..3 (compute phase)
    const int fl = tid & 63;       // col in tile
    const float* xr = binsR + (size_t)(bt0 + fr) * 4 * TF;
    const float* xi = binsI + (size_t)(bt0 + fr) * 4 * TF;

    const int wid  = tid >> 5, lane = tid & 31;
    const int gid  = lane >> 2, tig = lane & 3;
    const int mt   = wid & 3;      // m-tile == frame
    const int nh   = wid >> 2;     // n half (0/1)

    float acc[6][4];
    #pragma unroll
    for (int j = 0; j < 6; j++)
        #pragma unroll
        for (int v = 0; v < 4; v++) acc[j][v] = 0.0f;

    for (int it = 0; it < NTILE; ++it) {
        __syncthreads();    // previous tile fully consumed

        // ---- B tile copy (hi+lo), pre-padded/interleaved ----
        for (int i2 = tid; i2 < 1536; i2 += NT) {
            int split = i2 / 768, r = i2 % 768;
            int n = r >> 3, c4 = r & 7;
            const float4* src = (const float4*)(g_bt +
                ((size_t)split*96*512) + n*512 + it*KT + c4*8);
            *(float4*)(smraw + (split ? SM_B_LO : SM_B_HI) + n*ARS + c4*16) = *src;
        }

        // ---- A tile: fused phase1+2 adj comps, bf16 hi/lo ----
        {
            const int f = it * KT + fl;
            float comp[16];
            if (f < TF) {
                int lo = (f == 0) ? 0 : ((f == TF-1) ? TF-3 : f-1);
                int hi = lo + 2;
                float r0 = xr[f],      i0 = xi[f];
                float r1 = xr[TF+f],   i1 = xi[TF+f];
                float r2 = xr[2*TF+f], i2 = xi[2*TF+f];
                float r3 = xr[3*TF+f], i3 = xi[3*TF+f];
                float d0 = r0*r0+i0*i0, d1 = r1*r1+i1*i1;
                float d2 = r2*r2+i2*i2, d3 = r3*r3+i3*i3;
                float inv = 1.0f / fmaxf(d0+d1+d2+d3, 1e-20f);
                float pr[6], pi[6], lr[6], li[6], hr[6], hx[6];
#define PP(dr,di,s,Ri,Ii,Rj,Ij) dr[s] = Ri*Rj + Ii*Ij; di[s] = Ii*Rj - Ri*Ij;
                PP(pr,pi,0,r0,i0,r1,i1) PP(pr,pi,1,r0,i0,r2,i2) PP(pr,pi,2,r0,i0,r3,i3)
                PP(pr,pi,3,r1,i1,r2,i2) PP(pr,pi,4,r1,i1,r3,i3) PP(pr,pi,5,r2,i2,r3,i3)
                {
                    float a0 = xr[lo], b0 = xi[lo], a1 = xr[TF+lo], b1 = xi[TF+lo];
                    float a2 = xr[2*TF+lo], b2 = xi[2*TF+lo], a3 = xr[3*TF+lo], b3 = xi[3*TF+lo];
                    PP(lr,li,0,a0,b0,a1,b1) PP(lr,li,1,a0,b0,a2,b2) PP(lr,li,2,a0,b0,a3,b3)
                    PP(lr,li,3,a1,b1,a2,b2) PP(lr,li,4,a1,b1,a3,b3) PP(lr,li,5,a2,b2,a3,b3)
                    a0 = xr[hi]; b0 = xi[hi]; a1 = xr[TF+hi]; b1 = xi[TF+hi];
                    a2 = xr[2*TF+hi]; b2 = xi[2*TF+hi]; a3 = xr[3*TF+hi]; b3 = xi[3*TF+hi];
                    PP(hr,hx,0,a0,b0,a1,b1) PP(hr,hx,1,a0,b0,a2,b2) PP(hr,hx,2,a0,b0,a3,b3)
                    PP(hr,hx,3,a1,b1,a2,b2) PP(hr,hx,4,a1,b1,a3,b3) PP(hr,hx,5,a2,b2,a3,b3)
                }
#undef PP
                #pragma unroll
                for (int s = 0; s < 6; s++) {
                    float zr = lr[s]*hr[s] + li[s]*hx[s];
                    float zi = lr[s]*hx[s] - li[s]*hr[s];
                    float m  = sqrtf(pr[s]*pr[s] + pi[s]*pi[s]) * inv;
                    float z2 = zr*zr + zi*zi;
                    float aR, aI;
                    if (z2 > 0.0f) { float sc = m * rsqrtf(z2); aR = sc*zr; aI = sc*zi; }
                    else           { aR = m; aI = 0.0f; }
                    comp[2*s]   = aR;
                    comp[2*s+1] = aI;
                }
                comp[12] = d0*inv; comp[13] = d1*inv;
                comp[14] = d2*inv; comp[15] = d3*inv;
            } else {
                #pragma unroll
                for (int c = 0; c < 16; c++) comp[c] = 0.0f;
            }
            #pragma unroll
            for (int c = 0; c < 16; c++) {
                uint32_t off = (fr*16 + c)*ARS + fl*2;
                __nv_bfloat16 h = __float2bfloat16(comp[c]);
                *(__nv_bfloat16*)(smraw + SM_A_HI + off) = h;
                *(__nv_bfloat16*)(smraw + SM_A_LO + off) =
                    __float2bfloat16(comp[c] - __bfloat162float(h));
            }
        }
        __syncthreads();

        // ---- MMA: 4 ksteps x 6 n-tiles x 3 split products ----
        const int arow  = mt*16 + gid;
        #pragma unroll
        for (int ks = 0; ks < 4; ks++) {
            const int kb = (ks*16 + 2*tig)*2;   // byte offset of k pair
            uint32_t ah[4], al[4];
            ah[0] = *(const uint32_t*)(smraw + SM_A_HI + arow*ARS + kb);
            ah[1] = *(const uint32_t*)(smraw + SM_A_HI + (arow+8)*ARS + kb);
            ah[2] = *(const uint32_t*)(smraw + SM_A_HI + arow*ARS + kb + 16);
            ah[3] = *(const uint32_t*)(smraw + SM_A_HI + (arow+8)*ARS + kb + 16);
            al[0] = *(const uint32_t*)(smraw + SM_A_LO + arow*ARS + kb);
            al[1] = *(const uint32_t*)(smraw + SM_A_LO + (arow+8)*ARS + kb);
            al[2] = *(const uint32_t*)(smraw + SM_A_LO + arow*ARS + kb + 16);
            al[3] = *(const uint32_t*)(smraw + SM_A_LO + (arow+8)*ARS + kb + 16);
            #pragma unroll
            for (int j = 0; j < 6; j++) {
                const int n = (nh*6 + j)*8 + gid;
                uint32_t bh[2], bl[2];
                bh[0] = *(const uint32_t*)(smraw + SM_B_HI + n*ARS + kb);
                bh[1] = *(const uint32_t*)(smraw + SM_B_HI + n*ARS + kb + 16);
                bl[0] = *(const uint32_t*)(smraw + SM_B_LO + n*ARS + kb);
                bl[1] = *(const uint32_t*)(smraw + SM_B_LO + n*ARS + kb + 16);
                mma16816(acc[j], ah, bh);
                mma16816(acc[j], ah, bl);
                mma16816(acc[j], al, bh);
            }
        }
    }
    __syncthreads();   // A/B dead; safe to overlay

    // ---- epilogue: C fragments -> smem Cf[fr][c][BROW] ----
    {
        float* smf = (float*)(smraw + SM_CF);
        #pragma unroll
        for (int j = 0; j < 6; j++) {
            int col = (nh*6 + j)*8 + 2*tig;
            *(float2*)&smf[mt*1600 + gid*BROW + col]     = make_float2(acc[j][0], acc[j][1]);
            *(float2*)&smf[mt*1600 + (gid+8)*BROW + col] = make_float2(acc[j][2], acc[j][3]);
        }
    }
    __syncthreads();

    // ---- phase 4: reconstruct bc(complex 16) per k per frame ----
    for (int w = tid; w < NFR*192; w += NT) {
        int tl = w / 192, rr = w % 192;
        int kp = rr >> 3, slot = rr & 7;
        const float* Cfin = (const float*)(smraw + SM_CF) + tl*1600;
        float* qsm = (float*)(smraw + SM_QSM) + tl*1536;
        int m0 = (slot < 6) ? 2*slot : 12 + 2*(slot-6);
        float4 rA = *(const float4*)&Cfin[m0*BROW + 4*kp];
        float4 rB = *(const float4*)&Cfin[(m0+1)*BROW + 4*kp];
        float A0=rA.x, A1=rA.y, A4=rA.z, A5=rA.w;
        float A2=rB.x, A3=rB.y, A6=rB.z, A7=rB.w;
        float* q0 = qsm + (2*kp)*32;
        float* q1 = q0 + 32;
        if (slot < 6) {
            int i = (slot < 3) ? 0 : ((slot < 5) ? 1 : 2);
            int j = (slot < 3) ? slot+1 : ((slot < 5) ? slot-1 : 3);
            int c1 = i*4 + j, c2 = j*4 + i;
            q0[c1] = A0 - A3; q0[16+c1] = A1 + A2;
            q0[c2] = A0 + A3; q0[16+c2] = A1 - A2;
            q1[c1] = A4 - A7; q1[16+c1] = A5 + A6;
            q1[c2] = A4 + A7; q1[16+c2] = A5 - A6;
        } else {
            int d  = (slot == 6) ? 0 : 2;
            int cA = d*5, cB = (d+1)*5;
            q0[cA] = A0; q0[16+cA] = A1; q0[cB] = A2; q0[16+cB] = A3;
            q1[cA] = A4; q1[16+cA] = A5; q1[cB] = A6; q1[16+cB] = A7;
        }
    }
    __syncthreads();

    // ---- phase 5: normalize + c2pv projection (real part) ----
    for (int o = tid; o < NFR*NK*16; o += NT) {
        int tl = o / 768, r = o % 768;
        int k = r >> 4, p = r & 15;
        const float* qk = (const float*)(smraw + SM_QSM) + tl*1536 + k*32;
        float ds = fmaxf(qk[0] + qk[5] + qk[10] + qk[15], 1e-20f);
        float acc2 = 0.0f;
        #pragma unroll
        for (int c = 0; c < 16; c++) {
            acc2 += c2sm[c*16 + p] * qk[c];
            acc2 -= c2sm[256 + c*16 + p] * qk[16 + c];
        }
        out[(((size_t)b*NK + k)*1024 + (t0 + tl))*16 + p] = acc2 / ds;
    }
}

// ---------------- stage 2: chunked parallel-scan IIR ----------------
__global__ __launch_bounds__(512) void pv_iir(float* __restrict__ out,
                                              const float* __restrict__ tau)
{
    __shared__ float tails[32*16];
    __shared__ float carry[32*16];
    const int bk  = blockIdx.x;
    const int k   = bk % NK;
    const int tid = threadIdx.x;
    const int chunk = tid >> 4, p = tid & 15;

    const float a  = expf(-10.0f / tau[k]);
    const float om = 1.0f - a;
    float* base = out + ((size_t)bk * 1024 + chunk * 32) * 16 + p;

    float x[32];
    #pragma unroll
    for (int j = 0; j < 32; j++) x[j] = base[j*16];

    float l[32];
    l[0] = (chunk == 0) ? x[0] : om * x[0];
    #pragma unroll
    for (int j = 1; j < 32; j++) l[j] = a*l[j-1] + om*x[j];

    tails[chunk*16 + p] = l[31];
    __syncthreads();

    if (tid < 16) {
        float A = expf(-320.0f / tau[k]);
        float s = 0.0f;
        #pragma unroll
        for (int c = 0; c < 32; c++) {
            carry[c*16 + tid] = s;
            s = tails[c*16 + tid] + A * s;
        }
    }
    __syncthreads();

    float cin = carry[chunk*16 + p];
    float pw = a;
    #pragma unroll
    for (int j = 0; j < 32; j++) {
        base[j*16] = l[j] + pw * cin;
        pw *= a;
    }
}

extern "C" void kernel_launch(void* const* d_in, const int* in_sizes, int n_in,
                              void* d_out, int out_size)
{
    const float* binsR = (const float*)d_in[0];
    const float* binsI = (const float*)d_in[1];
    const float* bandR = (const float*)d_in[2];
    const float* bandI = (const float*)d_in[3];
    const float* c2r   = (const float*)d_in[4];
    const float* c2i   = (const float*)d_in[5];
    const float* tau   = (const float*)d_in[6];
    float* out = (float*)d_out;

    cudaFuncSetAttribute(pv_stage1, cudaFuncAttributeMaxDynamicSharedMemorySize, SMEM_BYTES);

    pv_prep<<<(96*512 + 255)/256, 256>>>(bandR, bandI);
    pv_stage1<<<1024, NT, SMEM_BYTES>>>(binsR, binsI, c2r, c2i, out);
    pv_iir<<<4*NK, 512>>>(out, tau);
}

// round 10
// speedup vs baseline: 2.1976x; 1.0160x over previous
#include <cuda_runtime.h>
#include <cuda_bf16.h>
#include <math.h>
#include <cstdint>

#define TF 481
#define NK 48
#define NFR 8             // frames per block (M = 128)
#define NT 256
#define KT 64             // K cols per tile
#define NTILE 8           // 512 padded K
#define BROW 100

#define ARS 144           // A/B smem row stride bytes (72 bf16)
// smem map (bytes)
#define SM_A_HI 0         // 128*144 = 18432
#define SM_A_LO 18432
#define SM_B_HI 36864     // 96*144 = 13824
#define SM_B_LO 50688
#define SM_C2B  64512     // 512 floats
#define SMEM_BYTES 66560
// overlays (A/B dead after last MMA; per 4-frame epilogue pass)
#define SM_CF  0          // 4*16*100 floats = 25600 B
#define SM_QSM 25600      // 4*48*32 floats = 24576 B -> 50176

__device__ __align__(16) __nv_bfloat16 g_bt[2 * 96 * 512];   // [split][n][k]

// ---------------- prep: band -> bf16 hi/lo, interleaved n, padded K ----------------
__global__ void pv_prep(const float* __restrict__ bandR, const float* __restrict__ bandI)
{
    int i = blockIdx.x * 256 + threadIdx.x;
    if (i >= 96 * 512) return;
    int n = i >> 9, k = i & 511;
    float val = 0.0f;
    if (k < TF) val = (n & 1) ? bandI[k*NK + (n>>1)] : bandR[k*NK + (n>>1)];
    __nv_bfloat16 h = __float2bfloat16(val);
    __nv_bfloat16 l = __float2bfloat16(val - __bfloat162float(h));
    g_bt[i] = h;
    g_bt[96*512 + i] = l;
}

__device__ __forceinline__ void mma16816(float* c, const uint32_t* a, const uint32_t* b)
{
    asm volatile(
        "mma.sync.aligned.m16n8k16.row.col.f32.bf16.bf16.f32 "
        "{%0,%1,%2,%3}, {%4,%5,%6,%7}, {%8,%9}, {%0,%1,%2,%3};"
        : "+f"(c[0]), "+f"(c[1]), "+f"(c[2]), "+f"(c[3])
        : "r"(a[0]), "r"(a[1]), "r"(a[2]), "r"(a[3]), "r"(b[0]), "r"(b[1]));
}

// ---------------- stage 1: 8 frames per block, HMMA bf16-split GEMM ----------------
__global__ __launch_bounds__(NT, 2) void pv_stage1(
    const float* __restrict__ binsR, const float* __restrict__ binsI,
    const float* __restrict__ c2r,  const float* __restrict__ c2i,
    float* __restrict__ out)
{
    extern __shared__ char smraw[];
    float* c2sm = (float*)(smraw + SM_C2B);

    const int tid = threadIdx.x;
    const int bt0 = blockIdx.x * NFR;
    const int b   = bt0 >> 10;
    const int t0  = bt0 & 1023;

    for (int i = tid; i < 512; i += NT) {
        int v = i & 255;
        int p = v >> 4, c = v & 15;
        float val = (i < 256) ? c2r[i] : c2i[v];
        c2sm[(i < 256 ? 0 : 256) + c*16 + p] = val;
    }

    const int fr0 = tid >> 6;      // 0..3 (item u adds 4)
    const int fl  = tid & 63;

    const int wid  = tid >> 5, lane = tid & 31;
    const int gid  = lane >> 2, tig = lane & 3;
    const int mpr  = wid & 3;      // m-tile pair: m-tiles {2mpr, 2mpr+1}
    const int nh   = wid >> 2;     // n half (6 n-tiles each)

    float acc[2][6][4];
    #pragma unroll
    for (int u = 0; u < 2; u++)
        #pragma unroll
        for (int j = 0; j < 6; j++)
            #pragma unroll
            for (int v = 0; v < 4; v++) acc[u][j][v] = 0.0f;

    char* ahi = smraw + SM_A_HI;
    char* alo = smraw + SM_A_LO;

    for (int it = 0; it < NTILE; ++it) {
        __syncthreads();    // previous tile fully consumed

        // ---- B tile copy (hi+lo) ----
        for (int i2 = tid; i2 < 1536; i2 += NT) {
            int split = i2 / 768, r = i2 % 768;
            int n = r >> 3, c4 = r & 7;
            const float4* src = (const float4*)(g_bt +
                ((size_t)split*96*512) + n*512 + it*KT + c4*8);
            *(float4*)(smraw + (split ? SM_B_LO : SM_B_HI) + n*ARS + c4*16) = *src;
        }

        // ---- A tiles: fused phase1+2 adj comps, 2 frames per thread ----
        const int f = it * KT + fl;
        #pragma unroll
        for (int u = 0; u < 2; u++) {
            const int fr = u*4 + fr0;
            const uint32_t rowbase = (fr*16)*ARS + fl*2;
#define STC(c, val) { float _v = (val); __nv_bfloat16 _h = __float2bfloat16(_v); \
            *(__nv_bfloat16*)(ahi + rowbase + (c)*ARS) = _h; \
            *(__nv_bfloat16*)(alo + rowbase + (c)*ARS) = \
                __float2bfloat16(_v - __bfloat162float(_h)); }
            if (f < TF) {
                const float* xr = binsR + (size_t)(bt0 + fr) * 4 * TF;
                const float* xi = binsI + (size_t)(bt0 + fr) * 4 * TF;
                int lo = (f == 0) ? 0 : ((f == TF-1) ? TF-3 : f-1);
                int hi = lo + 2;
                float cr[4], ci[4], lr[4], li[4], hr[4], hx[4];
                #pragma unroll
                for (int ch = 0; ch < 4; ch++) {
                    cr[ch] = xr[ch*TF + f];  ci[ch] = xi[ch*TF + f];
                    lr[ch] = xr[ch*TF + lo]; li[ch] = xi[ch*TF + lo];
                    hr[ch] = xr[ch*TF + hi]; hx[ch] = xi[ch*TF + hi];
                }
                float d0 = cr[0]*cr[0]+ci[0]*ci[0];
                float d1 = cr[1]*cr[1]+ci[1]*ci[1];
                float d2 = cr[2]*cr[2]+ci[2]*ci[2];
                float d3 = cr[3]*cr[3]+ci[3]*ci[3];
                float inv = 1.0f / fmaxf(d0+d1+d2+d3, 1e-20f);
                STC(12, d0*inv) STC(13, d1*inv) STC(14, d2*inv) STC(15, d3*inv)
                const int SI[6] = {0,0,0,1,1,2};
                const int SJ[6] = {1,2,3,2,3,3};
                #pragma unroll
                for (int s = 0; s < 6; s++) {
                    const int i5 = SI[s], j5 = SJ[s];
                    float pcr = cr[i5]*cr[j5] + ci[i5]*ci[j5];
                    float pci = ci[i5]*cr[j5] - cr[i5]*ci[j5];
                    float plr = lr[i5]*lr[j5] + li[i5]*li[j5];
                    float pli = li[i5]*lr[j5] - lr[i5]*li[j5];
                    float phr = hr[i5]*hr[j5] + hx[i5]*hx[j5];
                    float phi = hx[i5]*hr[j5] - hr[i5]*hx[j5];
                    float zr = plr*phr + pli*phi;
                    float zi = plr*phi - pli*phr;
                    float m  = sqrtf(pcr*pcr + pci*pci) * inv;
                    float z2 = zr*zr + zi*zi;
                    float aR, aI;
                    if (z2 > 0.0f) { float sc = m * rsqrtf(z2); aR = sc*zr; aI = sc*zi; }
                    else           { aR = m; aI = 0.0f; }
                    STC(2*s, aR) STC(2*s+1, aI)
                }
            } else {
                #pragma unroll
                for (int c = 0; c < 16; c++) STC(c, 0.0f)
            }
#undef STC
        }
        __syncthreads();

        // ---- MMA: 4 ksteps x (2 m-tiles x 6 n-tiles) x 3 split products ----
        #pragma unroll
        for (int ks = 0; ks < 4; ks++) {
            const int kb = (ks*16 + 2*tig)*2;
            uint32_t ah[2][4], al[2][4];
            #pragma unroll
            for (int u = 0; u < 2; u++) {
                const int arow = (2*mpr + u)*16 + gid;
                ah[u][0] = *(const uint32_t*)(ahi + arow*ARS + kb);
                ah[u][1] = *(const uint32_t*)(ahi + (arow+8)*ARS + kb);
                ah[u][2] = *(const uint32_t*)(ahi + arow*ARS + kb + 16);
                ah[u][3] = *(const uint32_t*)(ahi + (arow+8)*ARS + kb + 16);
                al[u][0] = *(const uint32_t*)(alo + arow*ARS + kb);
                al[u][1] = *(const uint32_t*)(alo + (arow+8)*ARS + kb);
                al[u][2] = *(const uint32_t*)(alo + arow*ARS + kb + 16);
                al[u][3] = *(const uint32_t*)(alo + (arow+8)*ARS + kb + 16);
            }
            #pragma unroll
            for (int j = 0; j < 6; j++) {
                const int n = (nh*6 + j)*8 + gid;
                uint32_t bh[2], bl[2];
                bh[0] = *(const uint32_t*)(smraw + SM_B_HI + n*ARS + kb);
                bh[1] = *(const uint32_t*)(smraw + SM_B_HI + n*ARS + kb + 16);
                bl[0] = *(const uint32_t*)(smraw + SM_B_LO + n*ARS + kb);
                bl[1] = *(const uint32_t*)(smraw + SM_B_LO + n*ARS + kb + 16);
                #pragma unroll
                for (int u = 0; u < 2; u++) {
                    mma16816(acc[u][j], ah[u], bh);
                    mma16816(acc[u][j], ah[u], bl);
                    mma16816(acc[u][j], al[u], bh);
                }
            }
        }
    }

    // ---- epilogue: two passes of 4 frames (CF/QSM overlay A/B) ----
    for (int pass = 0; pass < 2; pass++) {
        __syncthreads();   // A/B (pass0) or previous pass smem fully consumed
        if ((mpr >> 1) == pass) {
            float* smf = (float*)(smraw + SM_CF);
            #pragma unroll
            for (int u = 0; u < 2; u++) {
                const int lf = 2*(mpr & 1) + u;
                #pragma unroll
                for (int j = 0; j < 6; j++) {
                    int col = (nh*6 + j)*8 + 2*tig;
                    *(float2*)&smf[lf*1600 + gid*BROW + col] =
                        make_float2(acc[u][j][0], acc[u][j][1]);
                    *(float2*)&smf[lf*1600 + (gid+8)*BROW + col] =
                        make_float2(acc[u][j][2], acc[u][j][3]);
                }
            }
        }
        __syncthreads();

        // phase 4: reconstruct bc(complex 16) per k per frame
        for (int w = tid; w < 4*192; w += NT) {
            int tl = w / 192, rr = w % 192;
            int kp = rr >> 3, slot = rr & 7;
            const float* Cfin = (const float*)(smraw + SM_CF) + tl*1600;
            float* qsm = (float*)(smraw + SM_QSM) + tl*1536;
            int m0 = (slot < 6) ? 2*slot : 12 + 2*(slot-6);
            float4 rA = *(const float4*)&Cfin[m0*BROW + 4*kp];
            float4 rB = *(const float4*)&Cfin[(m0+1)*BROW + 4*kp];
            float A0=rA.x, A1=rA.y, A4=rA.z, A5=rA.w;
            float A2=rB.x, A3=rB.y, A6=rB.z, A7=rB.w;
            float* q0 = qsm + (2*kp)*32;
            float* q1 = q0 + 32;
            if (slot < 6) {
                int i = (slot < 3) ? 0 : ((slot < 5) ? 1 : 2);
                int j = (slot < 3) ? slot+1 : ((slot < 5) ? slot-1 : 3);
                int c1 = i*4 + j, c2 = j*4 + i;
                q0[c1] = A0 - A3; q0[16+c1] = A1 + A2;
                q0[c2] = A0 + A3; q0[16+c2] = A1 - A2;
                q1[c1] = A4 - A7; q1[16+c1] = A5 + A6;
                q1[c2] = A4 + A7; q1[16+c2] = A5 - A6;
            } else {
                int d  = (slot == 6) ? 0 : 2;
                int cA = d*5, cB = (d+1)*5;
                q0[cA] = A0; q0[16+cA] = A1; q0[cB] = A2; q0[16+cB] = A3;
                q1[cA] = A4; q1[16+cA] = A5; q1[cB] = A6; q1[16+cB] = A7;
            }
        }
        __syncthreads();

        // phase 5: normalize + c2pv projection (real part)
        for (int o = tid; o < 4*NK*16; o += NT) {
            int tl = o / 768, r = o % 768;
            int k = r >> 4, p = r & 15;
            const float* qk = (const float*)(smraw + SM_QSM) + tl*1536 + k*32;
            float ds = fmaxf(qk[0] + qk[5] + qk[10] + qk[15], 1e-20f);
            float acc2 = 0.0f;
            #pragma unroll
            for (int c = 0; c < 16; c++) {
                acc2 += c2sm[c*16 + p] * qk[c];
                acc2 -= c2sm[256 + c*16 + p] * qk[16 + c];
            }
            out[(((size_t)b*NK + k)*1024 + (t0 + pass*4 + tl))*16 + p] = acc2 / ds;
        }
    }
}

// ---------------- stage 2: chunked parallel-scan IIR ----------------
__global__ __launch_bounds__(512) void pv_iir(float* __restrict__ out,
                                              const float* __restrict__ tau)
{
    __shared__ float tails[32*16];
    __shared__ float carry[32*16];
    const int bk  = blockIdx.x;
    const int k   = bk % NK;
    const int tid = threadIdx.x;
    const int chunk = tid >> 4, p = tid & 15;

    const float a  = expf(-10.0f / tau[k]);
    const float om = 1.0f - a;
    float* base = out + ((size_t)bk * 1024 + chunk * 32) * 16 + p;

    float x[32];
    #pragma unroll
    for (int j = 0; j < 32; j++) x[j] = base[j*16];

    float l[32];
    l[0] = (chunk == 0) ? x[0] : om * x[0];
    #pragma unroll
    for (int j = 1; j < 32; j++) l[j] = a*l[j-1] + om*x[j];

    tails[chunk*16 + p] = l[31];
    __syncthreads();

    if (tid < 16) {
        float A = expf(-320.0f / tau[k]);
        float s = 0.0f;
        #pragma unroll
        for (int c = 0; c < 32; c++) {
            carry[c*16 + tid] = s;
            s = tails[c*16 + tid] + A * s;
        }
    }
    __syncthreads();

    float cin = carry[chunk*16 + p];
    float pw = a;
    #pragma unroll
    for (int j = 0; j < 32; j++) {
        base[j*16] = l[j] + pw * cin;
        pw *= a;
    }
}

extern "C" void kernel_launch(void* const* d_in, const int* in_sizes, int n_in,
                              void* d_out, int out_size)
{
    const float* binsR = (const float*)d_in[0];
    const float* binsI = (const float*)d_in[1];
    const float* bandR = (const float*)d_in[2];
    const float* bandI = (const float*)d_in[3];
    const float* c2r   = (const float*)d_in[4];
    const float* c2i   = (const float*)d_in[5];
    const float* tau   = (const float*)d_in[6];
    float* out = (float*)d_out;

    cudaFuncSetAttribute(pv_stage1, cudaFuncAttributeMaxDynamicSharedMemorySize, SMEM_BYTES);

    pv_prep<<<(96*512 + 255)/256, 256>>>(bandR, bandI);
    pv_stage1<<<512, NT, SMEM_BYTES>>>(binsR, binsI, c2r, c2i, out);
    pv_iir<<<4*NK, 512>>>(out, tau);
}